// round 7
// baseline (speedup 1.0000x reference)
#include <cuda_runtime.h>
#include <cuda_bf16.h>

// preds: [128, 4096, 50] float32 -> 26,214,400 elems (d_in[0])
// gt:    [128, 4096]     int32   ->    524,288 elems (d_in[1])
// out:   scalar float32
//
// SINGLE-PASS fused kernel: streaming softplus + in-register dot + count.
// 2 rows = 100 elems = exactly 25 float4s ("tile"). Grid stride divisible by
// 25 makes each thread's tile position jj = gtid%25 loop-invariant: bins,
// row offsets, and the spanning case (jj==12) are per-thread constants; the
// row index is maintained incrementally (no division in the loop).
// Unvoiced masking: product factor = 1 + w*exp(p) == 1 when w=0; dot masked
// by poisoning q. No scattered gather phase -> no L1tex wavefront bottleneck.

#define NF4       6553600u
#define ROWS      524288u
#define NBINS     50

#define SP_BLOCKS  1175u         // 47*25 -> NTHREADS divisible by 25; <=1184 (one wave)
#define SP_THREADS 256u
#define NTHREADS   (SP_BLOCKS * SP_THREADS)   // 300800
#define TILE_STR   (NTHREADS / 25u)           // 12032 tiles per loop step

__device__ float    g_part[SP_BLOCKS];
__device__ float    g_cntp[SP_BLOCKS];
__device__ unsigned g_done;

__device__ __forceinline__ float gk(int i) {
    const float K0 = 2.6386456e-4f;
    const float K1 = 0.10645078f;
    const float K2 = 0.78657072f;
    return (i == 2) ? K2 : ((i == 1 || i == 3) ? K1 : K0);
}

__global__ __launch_bounds__(SP_THREADS, 8) void pitchloss_kernel(
    const float* __restrict__ preds, const int* __restrict__ gt,
    float* __restrict__ out)
{
    // tab[q*5 + (d+2)] = blurred one-hot value at bin n=q+d (reflect handled).
    __shared__ float tab[NBINS * 5];
    const int tid = threadIdx.x;
    if (tid < NBINS * 5) {
        int q = tid / 5, di = tid % 5;
        int n = q + di - 2;
        float t = 0.0f;
        if (n >= 0 && n < NBINS) {
            #pragma unroll
            for (int i = 0; i < 5; i++) {
                int m  = n + i - 2;
                int mm = (m < 0) ? -m : ((m > NBINS - 1) ? (2 * (NBINS - 1) - m) : m);
                if (mm == q) t += gk(i);
            }
        }
        tab[tid] = t;
    }
    __syncthreads();

    const unsigned gtid = blockIdx.x * SP_THREADS + tid;
    const unsigned jj   = gtid % 25u;          // float4 position within tile
    const unsigned T0   = gtid / 25u;          // starting tile
    const int eloc  = 4 * (int)jj;             // 0..96
    const int a_off = (eloc >= 50) ? 1 : 0;    // row of elems 0,1 within tile
    const int b_off = (eloc >= 48) ? 1 : 0;    // row of elems 2,3
    const int na    = eloc - 50 * a_off;       // bin of element 0
    const int nb    = (eloc == 48) ? 0 : (na + 2);  // bin of element 2
    const float cwa = (na == 0) ? 1.0f : 0.0f;      // counts row-a start
    const float cwb = (eloc == 48) ? 1.0f : 0.0f;   // counts row-b start

    float acc = 0.0f, dot = 0.0f, cntf = 0.0f;
    const float4* p4 = reinterpret_cast<const float4*>(preds);

    unsigned r2 = 2u * T0;
    for (unsigned i = gtid; i < NF4; i += NTHREADS, r2 += 2u * TILE_STR) {
        float4 v = p4[i];
        int ga = __ldg(gt + r2 + a_off);
        int gb = __ldg(gt + r2 + b_off);

        int qa = min(max((ga - 50) / 6, 0), NBINS - 1);
        int qb = min(max((gb - 50) / 6, 0), NBINS - 1);
        bool va = (ga != 100), vb = (gb != 100);
        qa = va ? qa : 0x40000;                 // poison -> dot check fails
        qb = vb ? qb : 0x40000;
        float wa = va ? 1.0f : 0.0f;
        float wb = vb ? 1.0f : 0.0f;

        // dot: elems 0,1 vs row-a, elems 2,3 vs row-b
        int d0 = na - qa + 2;
        int d2 = nb - qb + 2;
        if ((unsigned)d0       < 5u) dot = fmaf(v.x, tab[qa * 5 + d0],     dot);
        if ((unsigned)(d0 + 1) < 5u) dot = fmaf(v.y, tab[qa * 5 + d0 + 1], dot);
        if ((unsigned)d2       < 5u) dot = fmaf(v.z, tab[qb * 5 + d2],     dot);
        if ((unsigned)(d2 + 1) < 5u) dot = fmaf(v.w, tab[qb * 5 + d2 + 1], dot);

        // masked softplus: prod of (1 + w*exp(p)); log2 once per float4
        float e0 = wa * __expf(v.x);
        float e1 = wa * __expf(v.y);
        float e2 = wb * __expf(v.z);
        float e3 = wb * __expf(v.w);
        float pr = 1.0f + e0;
        pr = fmaf(pr, e1, pr);
        pr = fmaf(pr, e2, pr);
        pr = fmaf(pr, e3, pr);
        acc += __log2f(pr);

        cntf = fmaf(cwa, wa, cntf);
        cntf = fmaf(cwb, wb, cntf);
    }

    // ---------------- block reduction -------------------------------------
    const float LN2 = 0.69314718055994530942f;
    float part = fmaf(LN2, acc, -dot);

    __shared__ float sp[SP_THREADS];
    __shared__ float sc[SP_THREADS];
    sp[tid] = part; sc[tid] = cntf;
    __syncthreads();
    #pragma unroll
    for (int o = SP_THREADS / 2; o > 0; o >>= 1) {
        if (tid < o) { sp[tid] += sp[tid + o]; sc[tid] += sc[tid + o]; }
        __syncthreads();
    }

    __shared__ bool s_last;
    if (tid == 0) {
        g_part[blockIdx.x] = sp[0];
        g_cntp[blockIdx.x] = sc[0];
        __threadfence();
        unsigned t = atomicAdd(&g_done, 1u);
        s_last = (t == SP_BLOCKS - 1);
    }
    __syncthreads();

    // ---------------- last block: deterministic ordered finalize ----------
    if (s_last) {
        float a = 0.0f, c = 0.0f;
        for (unsigned j = tid; j < SP_BLOCKS; j += SP_THREADS) {
            a += g_part[j]; c += g_cntp[j];
        }
        sp[tid] = a; sc[tid] = c;
        __syncthreads();
        #pragma unroll
        for (int o = SP_THREADS / 2; o > 0; o >>= 1) {
            if (tid < o) { sp[tid] += sp[tid + o]; sc[tid] += sc[tid + o]; }
            __syncthreads();
        }
        if (tid == 0) {
            out[0] = sp[0] / (50.0f * sc[0]);
            g_done = 0;   // reset for next (graph-replayed) launch
        }
    }
}

extern "C" void kernel_launch(void* const* d_in, const int* in_sizes, int n_in,
                              void* d_out, int out_size)
{
    const float* preds = (const float*)d_in[0];
    const int*   gt    = (const int*)d_in[1];
    float* out = (float*)d_out;

    pitchloss_kernel<<<SP_BLOCKS, SP_THREADS>>>(preds, gt, out);
}

// round 8
// speedup vs baseline: 1.0351x; 1.0351x over previous
#include <cuda_runtime.h>
#include <cuda_bf16.h>

// preds: [128, 4096, 50] float32 -> 26,214,400 elems (d_in[0])
// gt:    [128, 4096]     int32   ->    524,288 elems (d_in[1])
// out:   scalar float32
//
// loss = [ LN2*(sum_all log2(1+exp(p)) - sum_{unvoiced} log2(1+exp(p)))
//          - sum_{voiced} p.tgt ] / (50 * n_voiced)
//
// Two-phase fused kernel (R6 structure, best so far), with phase A dieted:
//  - smem table t6[q][0..5]: tgt values on the 8B-aligned 6-elem window
//    [2c, 2c+5], c = max(q-2,0)>>1, which always covers [q-2, q+2].
//    (rows start at 200B -> every row is 8B aligned -> float2 loads safe)
//  - 3x LDG.64 + 6 FFMA per voiced row (was: 5 scalar LDG + ~75 ALU recompute)
//  - gt in [0,199] => q <= 24 => window never crosses row end.

#define NF4       6553600u
#define ROWS      524288u
#define NBINS     50

#define SP_BLOCKS  1184u         // 148 * 8, single wave
#define SP_THREADS 256u
#define NTHREADS   (SP_BLOCKS * SP_THREADS)   // 303104

__device__ float    g_part[SP_BLOCKS];
__device__ int      g_cntp[SP_BLOCKS];
__device__ unsigned g_done;              // ticket; reset by last block

__device__ __forceinline__ float gk(int i) {
    const float K0 = 2.6386456e-4f;
    const float K1 = 0.10645078f;
    const float K2 = 0.78657072f;
    return (i == 2) ? K2 : ((i == 1 || i == 3) ? K1 : K0);
}

// prod *= (1 + exp(p))  ==  fma(prod, exp(p), prod)
__device__ __forceinline__ void pmul(float& pr, float p) {
    pr = fmaf(pr, __expf(p), pr);
}

__global__ __launch_bounds__(SP_THREADS, 8) void pitchloss_kernel(
    const float* __restrict__ preds, const int* __restrict__ gt,
    float* __restrict__ out)
{
    // ---- build t6 table: 50 rows x 8 (6 used + 2 pad), 1600B smem --------
    __shared__ float t6[NBINS * 8];
    const int tid = threadIdx.x;
    for (int idx = tid; idx < NBINS * 8; idx += SP_THREADS) {
        int q = idx >> 3, j = idx & 7;
        float t = 0.0f;
        if (j < 6) {
            int c = (q >= 2) ? ((q - 2) >> 1) : 0;   // window start chunk
            int n = 2 * c + j;                        // absolute bin
            if (n < NBINS) {
                #pragma unroll
                for (int i = 0; i < 5; i++) {
                    int m  = n + i - 2;
                    int mm = (m < 0) ? -m : ((m > NBINS - 1) ? (2*(NBINS-1) - m) : m);
                    if (mm == q) t += gk(i);
                }
            }
        }
        t6[idx] = t;
    }
    __syncthreads();

    const unsigned gtid = blockIdx.x * SP_THREADS + tid;

    // ---------------- phase A: per-row work --------------------------------
    float dot = 0.0f, neg = 0.0f;
    int   cnt = 0;
    for (unsigned r = gtid; r < ROWS; r += NTHREADS) {
        int g = gt[r];
        const float2* rp2 = reinterpret_cast<const float2*>(preds + (size_t)r * NBINS);
        if (g != 100) {
            cnt++;
            int q = (g > 50) ? min((g - 50) / 6, NBINS - 1) : 0;
            int c = (q >= 2) ? ((q - 2) >> 1) : 0;
            float2 a = __ldg(rp2 + c);
            float2 b = __ldg(rp2 + c + 1);
            float2 d = __ldg(rp2 + c + 2);
            const float* t = &t6[q * 8];
            dot = fmaf(a.x, t[0], dot);
            dot = fmaf(a.y, t[1], dot);
            dot = fmaf(b.x, t[2], dot);
            dot = fmaf(b.y, t[3], dot);
            dot = fmaf(d.x, t[4], dot);
            dot = fmaf(d.y, t[5], dot);
        } else {
            // rare (~0.5%): row softplus correction, log-product per 8 elems
            #pragma unroll
            for (int kk = 0; kk < 24; kk += 4) {
                float2 v0 = __ldg(rp2 + kk);
                float2 v1 = __ldg(rp2 + kk + 1);
                float2 v2 = __ldg(rp2 + kk + 2);
                float2 v3 = __ldg(rp2 + kk + 3);
                float pr = 1.0f + __expf(v0.x);
                pmul(pr, v0.y); pmul(pr, v1.x); pmul(pr, v1.y);
                pmul(pr, v2.x); pmul(pr, v2.y); pmul(pr, v3.x); pmul(pr, v3.y);
                neg += __log2f(pr);
            }
            float2 vl = __ldg(rp2 + 24);
            float pr = 1.0f + __expf(vl.x);
            pmul(pr, vl.y);
            neg += __log2f(pr);
        }
    }

    // ---------------- phase B: streaming softplus over ALL elements -------
    const float4* p4 = reinterpret_cast<const float4*>(preds);
    float acc = 0.0f;
    unsigned i = gtid;
    for (; i + 3u * NTHREADS < NF4; i += 4u * NTHREADS) {
        float4 a = p4[i];
        float4 b = p4[i +      NTHREADS];
        float4 c = p4[i + 2u * NTHREADS];
        float4 d = p4[i + 3u * NTHREADS];
        float pr1 = 1.0f + __expf(a.x);
        pmul(pr1, a.y); pmul(pr1, a.z); pmul(pr1, a.w);
        pmul(pr1, b.x); pmul(pr1, b.y); pmul(pr1, b.z); pmul(pr1, b.w);
        float pr2 = 1.0f + __expf(c.x);
        pmul(pr2, c.y); pmul(pr2, c.z); pmul(pr2, c.w);
        pmul(pr2, d.x); pmul(pr2, d.y); pmul(pr2, d.z); pmul(pr2, d.w);
        acc += __log2f(pr1) + __log2f(pr2);
    }
    for (; i < NF4; i += NTHREADS) {
        float4 a = p4[i];
        float pr = 1.0f + __expf(a.x);
        pmul(pr, a.y); pmul(pr, a.z); pmul(pr, a.w);
        acc += __log2f(pr);
    }

    // ---------------- block reduction -------------------------------------
    const float LN2 = 0.69314718055994530942f;
    float part = fmaf(LN2, acc - neg, -dot);

    __shared__ float sp[SP_THREADS];
    __shared__ int   sc[SP_THREADS];
    sp[tid] = part; sc[tid] = cnt;
    __syncthreads();
    #pragma unroll
    for (int o = SP_THREADS / 2; o > 0; o >>= 1) {
        if (tid < o) { sp[tid] += sp[tid + o]; sc[tid] += sc[tid + o]; }
        __syncthreads();
    }

    __shared__ bool s_last;
    if (tid == 0) {
        g_part[blockIdx.x] = sp[0];
        g_cntp[blockIdx.x] = sc[0];
        __threadfence();
        unsigned t = atomicAdd(&g_done, 1u);
        s_last = (t == SP_BLOCKS - 1);
    }
    __syncthreads();

    // ---------------- last block: deterministic ordered finalize ----------
    if (s_last) {
        float a = 0.0f; int c = 0;
        for (unsigned j = tid; j < SP_BLOCKS; j += SP_THREADS) {
            a += g_part[j]; c += g_cntp[j];
        }
        sp[tid] = a; sc[tid] = c;
        __syncthreads();
        #pragma unroll
        for (int o = SP_THREADS / 2; o > 0; o >>= 1) {
            if (tid < o) { sp[tid] += sp[tid + o]; sc[tid] += sc[tid + o]; }
            __syncthreads();
        }
        if (tid == 0) {
            out[0] = sp[0] / (50.0f * (float)sc[0]);
            g_done = 0;   // reset for next (graph-replayed) launch
        }
    }
}

extern "C" void kernel_launch(void* const* d_in, const int* in_sizes, int n_in,
                              void* d_out, int out_size)
{
    const float* preds = (const float*)d_in[0];
    const int*   gt    = (const int*)d_in[1];
    float* out = (float*)d_out;

    pitchloss_kernel<<<SP_BLOCKS, SP_THREADS>>>(preds, gt, out);
}

// round 9
// speedup vs baseline: 1.1558x; 1.1166x over previous
#include <cuda_runtime.h>
#include <cuda_bf16.h>

// preds: [128, 4096, 50] float32 -> 26,214,400 elems (d_in[0])
// gt:    [128, 4096]     int32   ->    524,288 elems (d_in[1])
// out:   scalar float32
//
// loss = [ LN2*(sum_all log2(1+exp(p)) - sum_{unvoiced} log2(1+exp(p)))
//          - sum_{voiced} p.tgt ] / (50 * n_voiced)
//
// WARP-SPECIALIZED fused kernel (R6 code, phases made concurrent):
//   warps 0-1: phase A (per-row gather: voiced dot / unvoiced correction)
//   warps 2-7: phase B (coalesced streaming softplus over all elements)
// Phase A's L1tex-wavefront + latency cost hides under phase B's DRAM stream
// (B uses ~3us of L1 wavefront capacity; A needs ~9us; stream takes ~20us).
// No sync between phases; they meet at the block reduction.

#define NF4       6553600u
#define ROWS      524288u
#define NBINS     50

#define SP_BLOCKS  1184u          // 148 * 8, single wave
#define SP_THREADS 256u
#define A_WARPS    2u
#define A_THREADS  (A_WARPS * 32u)                  // 64 per block
#define B_THREADS  (SP_THREADS - A_THREADS)         // 192 per block
#define NTH_A      (SP_BLOCKS * A_THREADS)          // 75776
#define NTH_B      (SP_BLOCKS * B_THREADS)          // 227328

__device__ float    g_part[SP_BLOCKS];
__device__ int      g_cntp[SP_BLOCKS];
__device__ unsigned g_done;               // ticket; reset by last block

__device__ __forceinline__ float gk(int i) {
    const float K0 = 2.6386456e-4f;
    const float K1 = 0.10645078f;
    const float K2 = 0.78657072f;
    return (i == 2) ? K2 : ((i == 1 || i == 3) ? K1 : K0);
}

__device__ __forceinline__ float sp2(float p) {   // log2(1 + exp(p))
    return __log2f(1.0f + __expf(p));
}

// prod *= (1 + exp(p))  ==  fma(prod, exp(p), prod)
__device__ __forceinline__ void pmul(float& pr, float p) {
    pr = fmaf(pr, __expf(p), pr);
}

__global__ __launch_bounds__(SP_THREADS, 8) void pitchloss_kernel(
    const float* __restrict__ preds, const int* __restrict__ gt,
    float* __restrict__ out)
{
    const int tid = threadIdx.x;
    const int wid = tid >> 5;

    float acc = 0.0f, dot = 0.0f, neg = 0.0f;
    int   cnt = 0;

    if (wid < (int)A_WARPS) {
        // ------------- phase A: per-row gather (2 warps/block) -------------
        const unsigned atid = blockIdx.x * A_THREADS + tid;
        for (unsigned r = atid; r < ROWS; r += NTH_A) {
            int g = __ldg(gt + r);
            const float* row = preds + (size_t)r * NBINS;
            if (g != 100) {
                cnt++;
                int q = (g > 50) ? min((g - 50) / 6, NBINS - 1) : 0;
                #pragma unroll
                for (int j = -2; j <= 2; j++) {
                    int n = q + j;
                    if (n < 0 || n > NBINS - 1) continue;
                    float t = 0.0f;
                    #pragma unroll
                    for (int i2 = 0; i2 < 5; i2++) {
                        int m  = n + i2 - 2;
                        int mm = (m < 0) ? -m : ((m > NBINS - 1) ? (2*(NBINS-1) - m) : m);
                        if (mm == q) t += gk(i2);
                    }
                    dot = fmaf(__ldg(row + n), t, dot);
                }
            } else {
                #pragma unroll 5
                for (int n = 0; n < NBINS; n++)
                    neg += sp2(__ldg(row + n));
            }
        }
    } else {
        // ------------- phase B: streaming softplus (6 warps/block) ---------
        const unsigned btid = blockIdx.x * B_THREADS + (unsigned)(tid - (int)A_THREADS);
        const float4* p4 = reinterpret_cast<const float4*>(preds);
        unsigned i = btid;
        for (; i + 3u * NTH_B < NF4; i += 4u * NTH_B) {
            float4 a = p4[i];
            float4 b = p4[i +      NTH_B];
            float4 c = p4[i + 2u * NTH_B];
            float4 d = p4[i + 3u * NTH_B];
            float pr1 = 1.0f + __expf(a.x);
            pmul(pr1, a.y); pmul(pr1, a.z); pmul(pr1, a.w);
            pmul(pr1, b.x); pmul(pr1, b.y); pmul(pr1, b.z); pmul(pr1, b.w);
            float pr2 = 1.0f + __expf(c.x);
            pmul(pr2, c.y); pmul(pr2, c.z); pmul(pr2, c.w);
            pmul(pr2, d.x); pmul(pr2, d.y); pmul(pr2, d.z); pmul(pr2, d.w);
            acc += __log2f(pr1) + __log2f(pr2);
        }
        for (; i < NF4; i += NTH_B) {
            float4 a = p4[i];
            float pr = 1.0f + __expf(a.x);
            pmul(pr, a.y); pmul(pr, a.z); pmul(pr, a.w);
            acc += __log2f(pr);
        }
    }

    // ---------------- block reduction -------------------------------------
    const float LN2 = 0.69314718055994530942f;
    float part = fmaf(LN2, acc - neg, -dot);

    __shared__ float sp[SP_THREADS];
    __shared__ int   sc[SP_THREADS];
    sp[tid] = part; sc[tid] = cnt;
    __syncthreads();
    #pragma unroll
    for (int o = SP_THREADS / 2; o > 0; o >>= 1) {
        if (tid < o) { sp[tid] += sp[tid + o]; sc[tid] += sc[tid + o]; }
        __syncthreads();
    }

    __shared__ bool s_last;
    if (tid == 0) {
        g_part[blockIdx.x] = sp[0];
        g_cntp[blockIdx.x] = sc[0];
        __threadfence();
        unsigned t = atomicAdd(&g_done, 1u);
        s_last = (t == SP_BLOCKS - 1);
    }
    __syncthreads();

    // ---------------- last block: deterministic ordered finalize ----------
    if (s_last) {
        float a = 0.0f; int c = 0;
        for (unsigned j = tid; j < SP_BLOCKS; j += SP_THREADS) {
            a += g_part[j]; c += g_cntp[j];
        }
        sp[tid] = a; sc[tid] = c;
        __syncthreads();
        #pragma unroll
        for (int o = SP_THREADS / 2; o > 0; o >>= 1) {
            if (tid < o) { sp[tid] += sp[tid + o]; sc[tid] += sc[tid + o]; }
            __syncthreads();
        }
        if (tid == 0) {
            out[0] = sp[0] / (50.0f * (float)sc[0]);
            g_done = 0;   // reset for next (graph-replayed) launch
        }
    }
}

extern "C" void kernel_launch(void* const* d_in, const int* in_sizes, int n_in,
                              void* d_out, int out_size)
{
    const float* preds = (const float*)d_in[0];
    const int*   gt    = (const int*)d_in[1];
    float* out = (float*)d_out;

    pitchloss_kernel<<<SP_BLOCKS, SP_THREADS>>>(preds, gt, out);
}